// round 8
// baseline (speedup 1.0000x reference)
#include <cuda_runtime.h>

#define LL 512
#define HH 512
#define G4 2048
#define DIN 320

// ---------------- scratch (no allocation allowed) ----------------
__device__ float g_x0 [LL * DIN];
__device__ float g_Za [LL * G4];
__device__ float g_Zb [LL * G4];
__device__ float g_hs0[LL * 2 * HH];
__device__ float g_hs1[LL * 2 * HH];
__device__ float g_mlp[LL * HH];
__device__ int   g_cnt[2 * 2 * LL];   // [layer][dir][t]

// ---------------- zero flags ----------------
__global__ void zero_cnt_kernel() {
    int i = blockIdx.x * blockDim.x + threadIdx.x;
    if (i < 2 * 2 * LL) g_cnt[i] = 0;
}

// ---------------- embedding gather ----------------
__global__ void embed_kernel(const int* __restrict__ wi, const int* __restrict__ pi,
                             const float* __restrict__ we, const float* __restrict__ pe) {
    int t = blockIdx.x;
    int i = threadIdx.x;              // 256 threads
    int w = wi[t], p = pi[t];
    g_x0[t * DIN + i] = we[w * 256 + i];
    if (i < 64) g_x0[t * DIN + 256 + i] = pe[p * 64 + i];
}

// ---------------- generic fp32 GEMM: C[M,N] = A[M,K] * B[N,K]^T + bias1 + bias2 ----------------
// Tiles padded to stride 68 (16B aligned, conflict-free LDS.128 fragment loads).
__global__ __launch_bounds__(256) void gemm_bias_kernel(
    const float* __restrict__ A, const float* __restrict__ B,
    const float* __restrict__ bias1, const float* __restrict__ bias2,
    float* __restrict__ C, int M, int N, int K)
{
    __shared__ __align__(16) float As[32][68];
    __shared__ __align__(16) float Bs[32][68];
    const int bn0 = blockIdx.x * 64;
    const int bm0 = blockIdx.y * 64;
    const int tid = threadIdx.x;
    const int tx = tid & 15, ty = tid >> 4;

    float acc[4][4];
    #pragma unroll
    for (int i = 0; i < 4; i++)
        #pragma unroll
        for (int j = 0; j < 4; j++) acc[i][j] = 0.f;

    for (int k0 = 0; k0 < K; k0 += 32) {
        #pragma unroll
        for (int i = 0; i < 8; i++) {
            int idx = tid + i * 256;
            int m = idx >> 5, k = idx & 31;     // coalesced global rows
            As[k][m] = (k0 + k < K) ? A[(bm0 + m) * K + k0 + k] : 0.f;
            Bs[k][m] = (k0 + k < K) ? B[(bn0 + m) * K + k0 + k] : 0.f;
        }
        __syncthreads();
        #pragma unroll
        for (int k = 0; k < 32; k++) {
            float4 av = *(const float4*)&As[k][ty * 4];   // LDS.128, 2-addr broadcast
            float4 bv = *(const float4*)&Bs[k][tx * 4];   // LDS.128, conflict-free
            acc[0][0] = fmaf(av.x, bv.x, acc[0][0]); acc[0][1] = fmaf(av.x, bv.y, acc[0][1]);
            acc[0][2] = fmaf(av.x, bv.z, acc[0][2]); acc[0][3] = fmaf(av.x, bv.w, acc[0][3]);
            acc[1][0] = fmaf(av.y, bv.x, acc[1][0]); acc[1][1] = fmaf(av.y, bv.y, acc[1][1]);
            acc[1][2] = fmaf(av.y, bv.z, acc[1][2]); acc[1][3] = fmaf(av.y, bv.w, acc[1][3]);
            acc[2][0] = fmaf(av.z, bv.x, acc[2][0]); acc[2][1] = fmaf(av.z, bv.y, acc[2][1]);
            acc[2][2] = fmaf(av.z, bv.z, acc[2][2]); acc[2][3] = fmaf(av.z, bv.w, acc[2][3]);
            acc[3][0] = fmaf(av.w, bv.x, acc[3][0]); acc[3][1] = fmaf(av.w, bv.y, acc[3][1]);
            acc[3][2] = fmaf(av.w, bv.z, acc[3][2]); acc[3][3] = fmaf(av.w, bv.w, acc[3][3]);
        }
        __syncthreads();
    }
    #pragma unroll
    for (int j = 0; j < 4; j++) {
        int n = bn0 + tx * 4 + j;
        float bv = bias1 ? bias1[n] : 0.f;
        if (bias2) bv += bias2[n];
        #pragma unroll
        for (int i = 0; i < 4; i++)
            C[(bm0 + ty * 4 + i) * N + n] = acc[i][j] + bv;
    }
}

// ---------------- persistent LSTM recurrence (both directions of one layer) ----------------
// grid = 128 blocks (64 fwd + 64 bwd), 256 threads. Each block owns 8 hidden units,
// keeps its 32 W_hh rows in registers (warp = 64-wide k slice, lane = gate row).
__global__ __launch_bounds__(256) void lstm_rec_kernel(
    const float* __restrict__ Zf, const float* __restrict__ Zb,
    const float* __restrict__ Whf, const float* __restrict__ Whb,
    float* __restrict__ hs, int* __restrict__ cnt)
{
    __shared__ __align__(16) float hsm[512];
    __shared__ float partial[8][33];

    const int dir = blockIdx.x >> 6;    // 0 fwd, 1 bwd
    const int blk = blockIdx.x & 63;
    const int j0  = blk * 8;
    const int tid = threadIdx.x;
    const int w   = tid >> 5;
    const int l   = tid & 31;
    const int u   = l >> 2;             // unit within block
    const int g   = l & 3;              // gate: 0=i 1=f 2=g 3=o
    const int grow = g * 512 + j0 + u;  // W_hh / Z row

    const float* W = dir ? Whb : Whf;
    const float* Z = dir ? Zb  : Zf;
    const int hofs = dir ? 512 : 0;
    int* mycnt = cnt + dir * 512;

    // weights resident in registers
    float4 wreg[16];
    const float4* wrow = (const float4*)(W + grow * 512 + w * 64);
    #pragma unroll
    for (int i = 0; i < 16; i++) wreg[i] = wrow[i];

    float c = 0.f;   // cell state (valid in warp 0, lanes with l%4==0)

    for (int s = 0; s < 512; s++) {
        const int t  = dir ? (511 - s) : s;
        const int tp = dir ? (t + 1)   : (t - 1);

        // hoist the Z load: immutable input, overlaps spin-wait + dot product
        float zpre = 0.f;
        if (w == 0) zpre = __ldg(&Z[t * 2048 + grow]);

        if (s == 0) {
            hsm[tid] = 0.f; hsm[tid + 256] = 0.f;
        } else {
            if (tid == 0) {
                volatile int* p = (volatile int*)&mycnt[tp];
                while (*p < 64) { }
                __threadfence();
            }
            __syncthreads();
            hsm[tid]       = __ldcg(&hs[tp * 1024 + hofs + tid]);
            hsm[tid + 256] = __ldcg(&hs[tp * 1024 + hofs + tid + 256]);
        }
        __syncthreads();

        // 4 independent accumulators: break the 64-deep serial FMA chain (256 cyc -> ~70 cyc)
        float a0 = 0.f, a1 = 0.f, a2 = 0.f, a3 = 0.f;
        #pragma unroll
        for (int i = 0; i < 16; i += 4) {
            float4 h0 = *(const float4*)&hsm[w * 64 + 4 * i];
            float4 h1 = *(const float4*)&hsm[w * 64 + 4 * (i + 1)];
            float4 h2 = *(const float4*)&hsm[w * 64 + 4 * (i + 2)];
            float4 h3 = *(const float4*)&hsm[w * 64 + 4 * (i + 3)];
            a0 = fmaf(wreg[i].x, h0.x, a0); a0 = fmaf(wreg[i].y, h0.y, a0);
            a0 = fmaf(wreg[i].z, h0.z, a0); a0 = fmaf(wreg[i].w, h0.w, a0);
            a1 = fmaf(wreg[i+1].x, h1.x, a1); a1 = fmaf(wreg[i+1].y, h1.y, a1);
            a1 = fmaf(wreg[i+1].z, h1.z, a1); a1 = fmaf(wreg[i+1].w, h1.w, a1);
            a2 = fmaf(wreg[i+2].x, h2.x, a2); a2 = fmaf(wreg[i+2].y, h2.y, a2);
            a2 = fmaf(wreg[i+2].z, h2.z, a2); a2 = fmaf(wreg[i+2].w, h2.w, a2);
            a3 = fmaf(wreg[i+3].x, h3.x, a3); a3 = fmaf(wreg[i+3].y, h3.y, a3);
            a3 = fmaf(wreg[i+3].z, h3.z, a3); a3 = fmaf(wreg[i+3].w, h3.w, a3);
        }
        partial[w][l] = (a0 + a1) + (a2 + a3);
        __syncthreads();

        if (w == 0) {
            // pairwise-tree 8-way reduction (shorter dependency chain than serial)
            float p0 = partial[0][l] + partial[1][l];
            float p1 = partial[2][l] + partial[3][l];
            float p2 = partial[4][l] + partial[5][l];
            float p3 = partial[6][l] + partial[7][l];
            float z  = zpre + ((p0 + p1) + (p2 + p3));
            float a = (g == 2) ? tanhf(z) : (1.f / (1.f + __expf(-z)));
            const unsigned mask = 0xffffffffu;
            float fv = __shfl_sync(mask, a, (l & ~3) + 1);
            float gv = __shfl_sync(mask, a, (l & ~3) + 2);
            float ov = __shfl_sync(mask, a, (l & ~3) + 3);
            if ((l & 3) == 0) {
                c = fmaf(fv, c, a * gv);
                float hv = ov * tanhf(c);
                hs[t * 1024 + hofs + j0 + u] = hv;
            }
            __syncwarp();
            __threadfence();
            if (l == 0) atomicAdd(&mycnt[t], 1);
        }
        // next iteration's first __syncthreads doubles as the post-finalize barrier
    }
}

// ---------------- pairwise scores: out[i][j] = out_b + sum_m tanh(mlp[i][m]+mlp[j+1][m])*w[m] ----------------
// B tile stored transposed (BsmT[m][j], stride 33) so the lane-indexed inner read is conflict-free.
__global__ __launch_bounds__(256) void pair_kernel(
    const float* __restrict__ mlp, const float* __restrict__ ow,
    const float* __restrict__ ob, float* __restrict__ out)
{
    __shared__ __align__(16) float Asm[32][132];
    __shared__ float BsmT[128][33];
    __shared__ float wsm[128];

    const int i0 = blockIdx.y * 32;
    const int j0 = blockIdx.x * 32;
    const int tid = threadIdx.x;
    const int ti = tid >> 5;           // warp id 0..7  -> i rows {ti, ti+8, ti+16, ti+24}
    const int tj = tid & 31;           // lane -> j column

    float acc0 = 0.f, acc1 = 0.f, acc2 = 0.f, acc3 = 0.f;

    for (int mc = 0; mc < 512; mc += 128) {
        const int row = tid >> 3, cg = tid & 7;
        {
            const float4* ap = (const float4*)&mlp[(i0 + row) * 512 + mc + cg * 16];
            float4* as = (float4*)&Asm[row][cg * 16];
            #pragma unroll
            for (int q = 0; q < 4; q++) as[q] = ap[q];
        }
        {
            const int brow = j0 + row + 1;
            float4 bp[4];
            if (brow < 512) {
                const float4* bg = (const float4*)&mlp[brow * 512 + mc + cg * 16];
                #pragma unroll
                for (int q = 0; q < 4; q++) bp[q] = bg[q];
            } else {
                float4 zz = make_float4(0.f, 0.f, 0.f, 0.f);
                #pragma unroll
                for (int q = 0; q < 4; q++) bp[q] = zz;
            }
            #pragma unroll
            for (int q = 0; q < 4; q++) {
                BsmT[cg * 16 + q * 4 + 0][row] = bp[q].x;
                BsmT[cg * 16 + q * 4 + 1][row] = bp[q].y;
                BsmT[cg * 16 + q * 4 + 2][row] = bp[q].z;
                BsmT[cg * 16 + q * 4 + 3][row] = bp[q].w;
            }
        }
        if (tid < 128) wsm[tid] = ow[mc + tid];
        __syncthreads();

        #pragma unroll 4
        for (int m = 0; m < 128; m++) {
            float b  = BsmT[m][tj];      // conflict-free: bank (m+tj)%32
            float wv = wsm[m];
            float a0 = Asm[ti][m];
            float a1 = Asm[ti + 8][m];
            float a2 = Asm[ti + 16][m];
            float a3 = Asm[ti + 24][m];
            float t0, t1, t2, t3;
            asm("tanh.approx.f32 %0, %1;" : "=f"(t0) : "f"(a0 + b));
            asm("tanh.approx.f32 %0, %1;" : "=f"(t1) : "f"(a1 + b));
            asm("tanh.approx.f32 %0, %1;" : "=f"(t2) : "f"(a2 + b));
            asm("tanh.approx.f32 %0, %1;" : "=f"(t3) : "f"(a3 + b));
            acc0 = fmaf(t0, wv, acc0);
            acc1 = fmaf(t1, wv, acc1);
            acc2 = fmaf(t2, wv, acc2);
            acc3 = fmaf(t3, wv, acc3);
        }
        __syncthreads();
    }

    const int j = j0 + tj;
    if (j < 511) {
        const float b = __ldg(ob);
        out[(i0 + ti)      * 511 + j] = acc0 + b;
        out[(i0 + ti + 8)  * 511 + j] = acc1 + b;
        out[(i0 + ti + 16) * 511 + j] = acc2 + b;
        out[(i0 + ti + 24) * 511 + j] = acc3 + b;
    }
}

// ---------------- launch ----------------
extern "C" void kernel_launch(void* const* d_in, const int* in_sizes, int n_in,
                              void* d_out, int out_size)
{
    const int*   wi      = (const int*)  d_in[0];
    const int*   pi      = (const int*)  d_in[1];
    const float* wemb    = (const float*)d_in[2];
    const float* pemb    = (const float*)d_in[3];
    const float* Wih0    = (const float*)d_in[4];
    const float* Whh0    = (const float*)d_in[5];
    const float* bih0    = (const float*)d_in[6];
    const float* bhh0    = (const float*)d_in[7];
    const float* Wih0r   = (const float*)d_in[8];
    const float* Whh0r   = (const float*)d_in[9];
    const float* bih0r   = (const float*)d_in[10];
    const float* bhh0r   = (const float*)d_in[11];
    const float* Wih1    = (const float*)d_in[12];
    const float* Whh1    = (const float*)d_in[13];
    const float* bih1    = (const float*)d_in[14];
    const float* bhh1    = (const float*)d_in[15];
    const float* Wih1r   = (const float*)d_in[16];
    const float* Whh1r   = (const float*)d_in[17];
    const float* bih1r   = (const float*)d_in[18];
    const float* bhh1r   = (const float*)d_in[19];
    const float* mlpW    = (const float*)d_in[20];
    const float* mlpBias = (const float*)d_in[21];
    const float* outw    = (const float*)d_in[22];
    const float* outb    = (const float*)d_in[23];

    float *x0, *Za, *Zb, *hs0, *hs1, *mlpbuf; int* cnt;
    cudaGetSymbolAddress((void**)&x0,     g_x0);
    cudaGetSymbolAddress((void**)&Za,     g_Za);
    cudaGetSymbolAddress((void**)&Zb,     g_Zb);
    cudaGetSymbolAddress((void**)&hs0,    g_hs0);
    cudaGetSymbolAddress((void**)&hs1,    g_hs1);
    cudaGetSymbolAddress((void**)&mlpbuf, g_mlp);
    cudaGetSymbolAddress((void**)&cnt,    g_cnt);

    zero_cnt_kernel<<<8, 256>>>();
    embed_kernel<<<LL, 256>>>(wi, pi, wemb, pemb);

    // layer 0 input projections
    gemm_bias_kernel<<<dim3(G4 / 64, LL / 64), 256>>>(x0, Wih0,  bih0,  bhh0,  Za, LL, G4, DIN);
    gemm_bias_kernel<<<dim3(G4 / 64, LL / 64), 256>>>(x0, Wih0r, bih0r, bhh0r, Zb, LL, G4, DIN);
    lstm_rec_kernel<<<128, 256>>>(Za, Zb, Whh0, Whh0r, hs0, cnt);

    // layer 1
    gemm_bias_kernel<<<dim3(G4 / 64, LL / 64), 256>>>(hs0, Wih1,  bih1,  bhh1,  Za, LL, G4, 1024);
    gemm_bias_kernel<<<dim3(G4 / 64, LL / 64), 256>>>(hs0, Wih1r, bih1r, bhh1r, Zb, LL, G4, 1024);
    lstm_rec_kernel<<<128, 256>>>(Za, Zb, Whh1, Whh1r, hs1, cnt + 1024);

    // MLP projection
    gemm_bias_kernel<<<dim3(HH / 64, LL / 64), 256>>>(hs1, mlpW, mlpBias, (const float*)nullptr,
                                                      mlpbuf, LL, HH, 1024);
    // pairwise scores
    pair_kernel<<<dim3(16, 16), 256>>>(mlpbuf, outw, outb, (float*)d_out);
}

// round 12
// speedup vs baseline: 1.2566x; 1.2566x over previous
#include <cuda_runtime.h>

#define LL 512
#define HH 512
#define G4 2048
#define DIN 320
#define FL_PER_LAYER (2 * 512 * 512)   // dirs * timesteps * units

// ---------------- scratch (no allocation allowed) ----------------
__device__ float g_x0 [LL * DIN];
__device__ float g_Za [LL * G4];
__device__ float g_Zb [LL * G4];
__device__ float g_hs0[LL * 2 * HH];
__device__ float g_hs1[LL * 2 * HH];
__device__ float g_mlp[LL * HH];
__device__ int   g_flg[2 * FL_PER_LAYER];   // [layer][dir][t][unit] ready flags

// ---------------- zero flags (1M ints = 4MB, int4 stores) ----------------
__global__ void zero_flags_kernel() {
    int i = blockIdx.x * blockDim.x + threadIdx.x;   // 1024*256 = 262144 int4
    ((int4*)g_flg)[i] = make_int4(0, 0, 0, 0);
}

// ---------------- embedding gather ----------------
__global__ void embed_kernel(const int* __restrict__ wi, const int* __restrict__ pi,
                             const float* __restrict__ we, const float* __restrict__ pe) {
    int t = blockIdx.x;
    int i = threadIdx.x;              // 256 threads
    int w = wi[t], p = pi[t];
    g_x0[t * DIN + i] = we[w * 256 + i];
    if (i < 64) g_x0[t * DIN + 256 + i] = pe[p * 64 + i];
}

// ---------------- generic fp32 GEMM: C[M,N] = A[M,K] * B[N,K]^T + bias1 + bias2 ----------------
__global__ __launch_bounds__(256) void gemm_bias_kernel(
    const float* __restrict__ A, const float* __restrict__ B,
    const float* __restrict__ bias1, const float* __restrict__ bias2,
    float* __restrict__ C, int M, int N, int K)
{
    __shared__ __align__(16) float As[32][68];
    __shared__ __align__(16) float Bs[32][68];
    const int bn0 = blockIdx.x * 64;
    const int bm0 = blockIdx.y * 64;
    const int tid = threadIdx.x;
    const int tx = tid & 15, ty = tid >> 4;

    float acc[4][4];
    #pragma unroll
    for (int i = 0; i < 4; i++)
        #pragma unroll
        for (int j = 0; j < 4; j++) acc[i][j] = 0.f;

    for (int k0 = 0; k0 < K; k0 += 32) {
        #pragma unroll
        for (int i = 0; i < 8; i++) {
            int idx = tid + i * 256;
            int m = idx >> 5, k = idx & 31;
            As[k][m] = (k0 + k < K) ? A[(bm0 + m) * K + k0 + k] : 0.f;
            Bs[k][m] = (k0 + k < K) ? B[(bn0 + m) * K + k0 + k] : 0.f;
        }
        __syncthreads();
        #pragma unroll
        for (int k = 0; k < 32; k++) {
            float4 av = *(const float4*)&As[k][ty * 4];
            float4 bv = *(const float4*)&Bs[k][tx * 4];
            acc[0][0] = fmaf(av.x, bv.x, acc[0][0]); acc[0][1] = fmaf(av.x, bv.y, acc[0][1]);
            acc[0][2] = fmaf(av.x, bv.z, acc[0][2]); acc[0][3] = fmaf(av.x, bv.w, acc[0][3]);
            acc[1][0] = fmaf(av.y, bv.x, acc[1][0]); acc[1][1] = fmaf(av.y, bv.y, acc[1][1]);
            acc[1][2] = fmaf(av.y, bv.z, acc[1][2]); acc[1][3] = fmaf(av.y, bv.w, acc[1][3]);
            acc[2][0] = fmaf(av.z, bv.x, acc[2][0]); acc[2][1] = fmaf(av.z, bv.y, acc[2][1]);
            acc[2][2] = fmaf(av.z, bv.z, acc[2][2]); acc[2][3] = fmaf(av.z, bv.w, acc[2][3]);
            acc[3][0] = fmaf(av.w, bv.x, acc[3][0]); acc[3][1] = fmaf(av.w, bv.y, acc[3][1]);
            acc[3][2] = fmaf(av.w, bv.z, acc[3][2]); acc[3][3] = fmaf(av.w, bv.w, acc[3][3]);
        }
        __syncthreads();
    }
    #pragma unroll
    for (int j = 0; j < 4; j++) {
        int n = bn0 + tx * 4 + j;
        float bv = bias1 ? bias1[n] : 0.f;
        if (bias2) bv += bias2[n];
        #pragma unroll
        for (int i = 0; i < 4; i++)
            C[(bm0 + ty * 4 + i) * N + n] = acc[i][j] + bv;
    }
}

// ---------------- persistent LSTM recurrence with release/acquire per-unit flags ----------------
// 128 blocks (64 fwd + 64 bwd) x 256 thr. Block owns 8 hidden units, W_hh rows in regs.
__global__ __launch_bounds__(256) void lstm_rec_kernel(
    const float* __restrict__ Zf, const float* __restrict__ Zb,
    const float* __restrict__ Whf, const float* __restrict__ Whb,
    float* __restrict__ hs, int* __restrict__ flags)
{
    __shared__ __align__(16) float hsm[512];
    __shared__ float partial[8][33];

    const int dir = blockIdx.x >> 6;
    const int blk = blockIdx.x & 63;
    const int j0  = blk * 8;
    const int tid = threadIdx.x;
    const int w   = tid >> 5;
    const int l   = tid & 31;
    const int u   = l >> 2;
    const int g   = l & 3;              // 0=i 1=f 2=g 3=o
    const int grow = g * 512 + j0 + u;

    const float* W = dir ? Whb : Whf;
    const float* Z = dir ? Zb  : Zf;
    const int hofs = dir ? 512 : 0;
    int* myflg = flags + dir * (512 * 512);

    float4 wreg[16];
    const float4* wrow = (const float4*)(W + grow * 512 + w * 64);
    #pragma unroll
    for (int i = 0; i < 16; i++) wreg[i] = wrow[i];

    float c = 0.f;

    for (int s = 0; s < 512; s++) {
        const int t  = dir ? (511 - s) : s;
        const int tp = dir ? (t + 1)   : (t - 1);

        // hoisted Z load overlaps the poll
        float zpre = 0.f;
        if (w == 0) zpre = __ldg(&Z[t * 2048 + grow]);

        if (s == 0) {
            hsm[tid] = 0.f; hsm[tid + 256] = 0.f;
        } else {
            // acquire-poll the 2 flags for the 2 h values this thread owns, then load them
            const unsigned long long* fp =
                (const unsigned long long*)(myflg + tp * 512) + tid;
            unsigned long long v;
            do {
                asm volatile("ld.acquire.gpu.global.b64 %0, [%1];" : "=l"(v) : "l"(fp));
            } while (v != 0x0000000100000001ULL);
            float2 h2 = __ldcg((const float2*)&hs[tp * 1024 + hofs] + tid);
            *(float2*)&hsm[2 * tid] = h2;
        }
        __syncthreads();

        // 4 independent accumulators: short dependency chains
        float a0 = 0.f, a1 = 0.f, a2 = 0.f, a3 = 0.f;
        #pragma unroll
        for (int i = 0; i < 16; i += 4) {
            float4 h0 = *(const float4*)&hsm[w * 64 + 4 * i];
            float4 h1 = *(const float4*)&hsm[w * 64 + 4 * (i + 1)];
            float4 h2 = *(const float4*)&hsm[w * 64 + 4 * (i + 2)];
            float4 h3 = *(const float4*)&hsm[w * 64 + 4 * (i + 3)];
            a0 = fmaf(wreg[i].x, h0.x, a0); a0 = fmaf(wreg[i].y, h0.y, a0);
            a0 = fmaf(wreg[i].z, h0.z, a0); a0 = fmaf(wreg[i].w, h0.w, a0);
            a1 = fmaf(wreg[i+1].x, h1.x, a1); a1 = fmaf(wreg[i+1].y, h1.y, a1);
            a1 = fmaf(wreg[i+1].z, h1.z, a1); a1 = fmaf(wreg[i+1].w, h1.w, a1);
            a2 = fmaf(wreg[i+2].x, h2.x, a2); a2 = fmaf(wreg[i+2].y, h2.y, a2);
            a2 = fmaf(wreg[i+2].z, h2.z, a2); a2 = fmaf(wreg[i+2].w, h2.w, a2);
            a3 = fmaf(wreg[i+3].x, h3.x, a3); a3 = fmaf(wreg[i+3].y, h3.y, a3);
            a3 = fmaf(wreg[i+3].z, h3.z, a3); a3 = fmaf(wreg[i+3].w, h3.w, a3);
        }
        partial[w][l] = (a0 + a1) + (a2 + a3);
        __syncthreads();

        if (w == 0) {
            float p0 = partial[0][l] + partial[1][l];
            float p1 = partial[2][l] + partial[3][l];
            float p2 = partial[4][l] + partial[5][l];
            float p3 = partial[6][l] + partial[7][l];
            float z  = zpre + ((p0 + p1) + (p2 + p3));
            // MUFU activations: tanh for gate g, sigmoid via 0.5*tanh(z/2)+0.5
            float targ = (g == 2) ? z : 0.5f * z;
            float th;
            asm("tanh.approx.f32 %0, %1;" : "=f"(th) : "f"(targ));
            float a = (g == 2) ? th : fmaf(0.5f, th, 0.5f);
            const unsigned mask = 0xffffffffu;
            float fv = __shfl_sync(mask, a, (l & ~3) + 1);
            float gv = __shfl_sync(mask, a, (l & ~3) + 2);
            float ov = __shfl_sync(mask, a, (l & ~3) + 3);
            if ((l & 3) == 0) {
                c = fmaf(fv, c, a * gv);
                float tc;
                asm("tanh.approx.f32 %0, %1;" : "=f"(tc) : "f"(c));
                float hv = ov * tc;
                hs[t * 1024 + hofs + j0 + u] = hv;                       // data
                asm volatile("st.release.gpu.global.b32 [%0], %1;"       // own flag
                             :: "l"(myflg + t * 512 + j0 + u), "r"(1) : "memory");
            }
        }
        // next step's first __syncthreads is the post-finalize barrier
    }
}

// ---------------- pairwise scores: out[i][j] = out_b + sum_m tanh(mlp[i][m]+mlp[j+1][m])*w[m] ----------------
__global__ __launch_bounds__(256) void pair_kernel(
    const float* __restrict__ mlp, const float* __restrict__ ow,
    const float* __restrict__ ob, float* __restrict__ out)
{
    __shared__ __align__(16) float Asm[32][132];
    __shared__ float BsmT[128][33];
    __shared__ float wsm[128];

    const int i0 = blockIdx.y * 32;
    const int j0 = blockIdx.x * 32;
    const int tid = threadIdx.x;
    const int ti = tid >> 5;
    const int tj = tid & 31;

    float acc0 = 0.f, acc1 = 0.f, acc2 = 0.f, acc3 = 0.f;

    for (int mc = 0; mc < 512; mc += 128) {
        const int row = tid >> 3, cg = tid & 7;
        {
            const float4* ap = (const float4*)&mlp[(i0 + row) * 512 + mc + cg * 16];
            float4* as = (float4*)&Asm[row][cg * 16];
            #pragma unroll
            for (int q = 0; q < 4; q++) as[q] = ap[q];
        }
        {
            const int brow = j0 + row + 1;
            float4 bp[4];
            if (brow < 512) {
                const float4* bg = (const float4*)&mlp[brow * 512 + mc + cg * 16];
                #pragma unroll
                for (int q = 0; q < 4; q++) bp[q] = bg[q];
            } else {
                float4 zz = make_float4(0.f, 0.f, 0.f, 0.f);
                #pragma unroll
                for (int q = 0; q < 4; q++) bp[q] = zz;
            }
            #pragma unroll
            for (int q = 0; q < 4; q++) {
                BsmT[cg * 16 + q * 4 + 0][row] = bp[q].x;
                BsmT[cg * 16 + q * 4 + 1][row] = bp[q].y;
                BsmT[cg * 16 + q * 4 + 2][row] = bp[q].z;
                BsmT[cg * 16 + q * 4 + 3][row] = bp[q].w;
            }
        }
        if (tid < 128) wsm[tid] = ow[mc + tid];
        __syncthreads();

        #pragma unroll 4
        for (int m = 0; m < 128; m++) {
            float b  = BsmT[m][tj];
            float wv = wsm[m];
            float a0 = Asm[ti][m];
            float a1 = Asm[ti + 8][m];
            float a2 = Asm[ti + 16][m];
            float a3 = Asm[ti + 24][m];
            float t0, t1, t2, t3;
            asm("tanh.approx.f32 %0, %1;" : "=f"(t0) : "f"(a0 + b));
            asm("tanh.approx.f32 %0, %1;" : "=f"(t1) : "f"(a1 + b));
            asm("tanh.approx.f32 %0, %1;" : "=f"(t2) : "f"(a2 + b));
            asm("tanh.approx.f32 %0, %1;" : "=f"(t3) : "f"(a3 + b));
            acc0 = fmaf(t0, wv, acc0);
            acc1 = fmaf(t1, wv, acc1);
            acc2 = fmaf(t2, wv, acc2);
            acc3 = fmaf(t3, wv, acc3);
        }
        __syncthreads();
    }

    const int j = j0 + tj;
    if (j < 511) {
        const float b = __ldg(ob);
        out[(i0 + ti)      * 511 + j] = acc0 + b;
        out[(i0 + ti + 8)  * 511 + j] = acc1 + b;
        out[(i0 + ti + 16) * 511 + j] = acc2 + b;
        out[(i0 + ti + 24) * 511 + j] = acc3 + b;
    }
}

// ---------------- launch ----------------
extern "C" void kernel_launch(void* const* d_in, const int* in_sizes, int n_in,
                              void* d_out, int out_size)
{
    const int*   wi      = (const int*)  d_in[0];
    const int*   pi      = (const int*)  d_in[1];
    const float* wemb    = (const float*)d_in[2];
    const float* pemb    = (const float*)d_in[3];
    const float* Wih0    = (const float*)d_in[4];
    const float* Whh0    = (const float*)d_in[5];
    const float* bih0    = (const float*)d_in[6];
    const float* bhh0    = (const float*)d_in[7];
    const float* Wih0r   = (const float*)d_in[8];
    const float* Whh0r   = (const float*)d_in[9];
    const float* bih0r   = (const float*)d_in[10];
    const float* bhh0r   = (const float*)d_in[11];
    const float* Wih1    = (const float*)d_in[12];
    const float* Whh1    = (const float*)d_in[13];
    const float* bih1    = (const float*)d_in[14];
    const float* bhh1    = (const float*)d_in[15];
    const float* Wih1r   = (const float*)d_in[16];
    const float* Whh1r   = (const float*)d_in[17];
    const float* bih1r   = (const float*)d_in[18];
    const float* bhh1r   = (const float*)d_in[19];
    const float* mlpW    = (const float*)d_in[20];
    const float* mlpBias = (const float*)d_in[21];
    const float* outw    = (const float*)d_in[22];
    const float* outb    = (const float*)d_in[23];

    float *x0, *Za, *Zb, *hs0, *hs1, *mlpbuf; int* flg;
    cudaGetSymbolAddress((void**)&x0,     g_x0);
    cudaGetSymbolAddress((void**)&Za,     g_Za);
    cudaGetSymbolAddress((void**)&Zb,     g_Zb);
    cudaGetSymbolAddress((void**)&hs0,    g_hs0);
    cudaGetSymbolAddress((void**)&hs1,    g_hs1);
    cudaGetSymbolAddress((void**)&mlpbuf, g_mlp);
    cudaGetSymbolAddress((void**)&flg,    g_flg);

    zero_flags_kernel<<<1024, 256>>>();
    embed_kernel<<<LL, 256>>>(wi, pi, wemb, pemb);

    // layer 0 input projections
    gemm_bias_kernel<<<dim3(G4 / 64, LL / 64), 256>>>(x0, Wih0,  bih0,  bhh0,  Za, LL, G4, DIN);
    gemm_bias_kernel<<<dim3(G4 / 64, LL / 64), 256>>>(x0, Wih0r, bih0r, bhh0r, Zb, LL, G4, DIN);
    lstm_rec_kernel<<<128, 256>>>(Za, Zb, Whh0, Whh0r, hs0, flg);

    // layer 1
    gemm_bias_kernel<<<dim3(G4 / 64, LL / 64), 256>>>(hs0, Wih1,  bih1,  bhh1,  Za, LL, G4, 1024);
    gemm_bias_kernel<<<dim3(G4 / 64, LL / 64), 256>>>(hs0, Wih1r, bih1r, bhh1r, Zb, LL, G4, 1024);
    lstm_rec_kernel<<<128, 256>>>(Za, Zb, Whh1, Whh1r, hs1, flg + FL_PER_LAYER);

    // MLP projection
    gemm_bias_kernel<<<dim3(HH / 64, LL / 64), 256>>>(hs1, mlpW, mlpBias, (const float*)nullptr,
                                                      mlpbuf, LL, HH, 1024);
    // pairwise scores
    pair_kernel<<<dim3(16, 16), 256>>>(mlpbuf, outw, outb, (float*)d_out);
}

// round 16
// speedup vs baseline: 1.2718x; 1.0121x over previous
#include <cuda_runtime.h>

#define LL 512
#define HH 512
#define G4 2048
#define DIN 320

// ---------------- scratch (no allocation allowed) ----------------
__device__ float g_x0 [LL * DIN];
__device__ float g_Za [LL * G4];
__device__ float g_Zb [LL * G4];
__device__ __align__(16) float g_hs0[LL * 2 * HH];
__device__ __align__(16) float g_hs1[LL * 2 * HH];
__device__ float g_mlp[LL * HH];
// packet mailboxes: one u64 per (dir, t, unit): high32 = ready flag, low32 = h bits
__device__ __align__(16) unsigned long long g_mb0[2 * 512 * 512];
__device__ __align__(16) unsigned long long g_mb1[2 * 512 * 512];

// ---------------- zero mailboxes: 2 x 4MB ----------------
__global__ void zero_mb_kernel() {
    int i = blockIdx.x * blockDim.x + threadIdx.x;   // 1024*256 = 262144 uint4 slots per array
    uint4 z = make_uint4(0, 0, 0, 0);
    ((uint4*)g_mb0)[i] = z;
    ((uint4*)g_mb1)[i] = z;
}

// ---------------- embedding gather ----------------
__global__ void embed_kernel(const int* __restrict__ wi, const int* __restrict__ pi,
                             const float* __restrict__ we, const float* __restrict__ pe) {
    int t = blockIdx.x;
    int i = threadIdx.x;              // 256 threads
    int w = wi[t], p = pi[t];
    g_x0[t * DIN + i] = we[w * 256 + i];
    if (i < 64) g_x0[t * DIN + 256 + i] = pe[p * 64 + i];
}

// ---------------- generic fp32 GEMM: C[M,N] = A[M,K] * B[N,K]^T + bias1 + bias2 ----------------
__global__ __launch_bounds__(256) void gemm_bias_kernel(
    const float* __restrict__ A, const float* __restrict__ B,
    const float* __restrict__ bias1, const float* __restrict__ bias2,
    float* __restrict__ C, int M, int N, int K)
{
    __shared__ __align__(16) float As[32][68];
    __shared__ __align__(16) float Bs[32][68];
    const int bn0 = blockIdx.x * 64;
    const int bm0 = blockIdx.y * 64;
    const int tid = threadIdx.x;
    const int tx = tid & 15, ty = tid >> 4;

    float acc[4][4];
    #pragma unroll
    for (int i = 0; i < 4; i++)
        #pragma unroll
        for (int j = 0; j < 4; j++) acc[i][j] = 0.f;

    for (int k0 = 0; k0 < K; k0 += 32) {
        #pragma unroll
        for (int i = 0; i < 8; i++) {
            int idx = tid + i * 256;
            int m = idx >> 5, k = idx & 31;
            As[k][m] = (k0 + k < K) ? A[(bm0 + m) * K + k0 + k] : 0.f;
            Bs[k][m] = (k0 + k < K) ? B[(bn0 + m) * K + k0 + k] : 0.f;
        }
        __syncthreads();
        #pragma unroll
        for (int k = 0; k < 32; k++) {
            float4 av = *(const float4*)&As[k][ty * 4];
            float4 bv = *(const float4*)&Bs[k][tx * 4];
            acc[0][0] = fmaf(av.x, bv.x, acc[0][0]); acc[0][1] = fmaf(av.x, bv.y, acc[0][1]);
            acc[0][2] = fmaf(av.x, bv.z, acc[0][2]); acc[0][3] = fmaf(av.x, bv.w, acc[0][3]);
            acc[1][0] = fmaf(av.y, bv.x, acc[1][0]); acc[1][1] = fmaf(av.y, bv.y, acc[1][1]);
            acc[1][2] = fmaf(av.y, bv.z, acc[1][2]); acc[1][3] = fmaf(av.y, bv.w, acc[1][3]);
            acc[2][0] = fmaf(av.z, bv.x, acc[2][0]); acc[2][1] = fmaf(av.z, bv.y, acc[2][1]);
            acc[2][2] = fmaf(av.z, bv.z, acc[2][2]); acc[2][3] = fmaf(av.z, bv.w, acc[2][3]);
            acc[3][0] = fmaf(av.w, bv.x, acc[3][0]); acc[3][1] = fmaf(av.w, bv.y, acc[3][1]);
            acc[3][2] = fmaf(av.w, bv.z, acc[3][2]); acc[3][3] = fmaf(av.w, bv.w, acc[3][3]);
        }
        __syncthreads();
    }
    #pragma unroll
    for (int j = 0; j < 4; j++) {
        int n = bn0 + tx * 4 + j;
        float bv = bias1 ? bias1[n] : 0.f;
        if (bias2) bv += bias2[n];
        #pragma unroll
        for (int i = 0; i < 4; i++)
            C[(bm0 + ty * 4 + i) * N + n] = acc[i][j] + bv;
    }
}

// ---------------- persistent LSTM recurrence, packet mailbox + acquire/release ----------------
// 128 blocks (64 fwd + 64 bwd) x 256 thr. Block owns 8 hidden units, W_hh rows in regs.
// Producer emits one 64-bit packet {flag=1 | h bits} per unit with st.release.gpu;
// consumer spins on ld.acquire.gpu (two scalar b64 loads, overlapped) until both flags set.
// Payload rides in the polled word -> no separate data round trip.
__global__ __launch_bounds__(256) void lstm_rec_kernel(
    const float* __restrict__ Zf, const float* __restrict__ Zb,
    const float* __restrict__ Whf, const float* __restrict__ Whb,
    float* __restrict__ hs, unsigned long long* __restrict__ mb)
{
    __shared__ __align__(16) float hsm[512];
    __shared__ float partial[8][33];

    const int dir = blockIdx.x >> 6;
    const int blk = blockIdx.x & 63;
    const int j0  = blk * 8;
    const int tid = threadIdx.x;
    const int w   = tid >> 5;
    const int l   = tid & 31;
    const int u   = l >> 2;
    const int g   = l & 3;              // 0=i 1=f 2=g 3=o
    const int grow = g * 512 + j0 + u;

    const float* W = dir ? Whb : Whf;
    const float* Z = dir ? Zb  : Zf;
    const int hofs = dir ? 512 : 0;
    unsigned long long* mymb = mb + dir * (512 * 512);

    float4 wreg[16];
    const float4* wrow = (const float4*)(W + grow * 512 + w * 64);
    #pragma unroll
    for (int i = 0; i < 16; i++) wreg[i] = wrow[i];

    float c = 0.f;

    for (int s = 0; s < 512; s++) {
        const int t  = dir ? (511 - s) : s;
        const int tp = dir ? (t + 1)   : (t - 1);

        // hoisted Z load overlaps the poll
        float zpre = 0.f;
        if (w == 0) zpre = __ldg(&Z[t * 2048 + grow]);

        if (s == 0) {
            hsm[tid] = 0.f; hsm[tid + 256] = 0.f;
        } else {
            // acquire-poll the two packets this thread owns; payload rides with the flag
            const unsigned long long* mp = mymb + tp * 512 + 2 * tid;
            unsigned long long v0, v1;
            do {
                asm volatile("ld.acquire.gpu.global.b64 %0, [%1];" : "=l"(v0) : "l"(mp));
                asm volatile("ld.acquire.gpu.global.b64 %0, [%1];" : "=l"(v1) : "l"(mp + 1));
            } while ((unsigned)(v0 >> 32) == 0u || (unsigned)(v1 >> 32) == 0u);
            hsm[2 * tid]     = __uint_as_float((unsigned)v0);
            hsm[2 * tid + 1] = __uint_as_float((unsigned)v1);
        }
        __syncthreads();

        // 4 independent accumulators: short dependency chains
        float a0 = 0.f, a1 = 0.f, a2 = 0.f, a3 = 0.f;
        #pragma unroll
        for (int i = 0; i < 16; i += 4) {
            float4 h0 = *(const float4*)&hsm[w * 64 + 4 * i];
            float4 h1 = *(const float4*)&hsm[w * 64 + 4 * (i + 1)];
            float4 h2 = *(const float4*)&hsm[w * 64 + 4 * (i + 2)];
            float4 h3 = *(const float4*)&hsm[w * 64 + 4 * (i + 3)];
            a0 = fmaf(wreg[i].x, h0.x, a0); a0 = fmaf(wreg[i].y, h0.y, a0);
            a0 = fmaf(wreg[i].z, h0.z, a0); a0 = fmaf(wreg[i].w, h0.w, a0);
            a1 = fmaf(wreg[i+1].x, h1.x, a1); a1 = fmaf(wreg[i+1].y, h1.y, a1);
            a1 = fmaf(wreg[i+1].z, h1.z, a1); a1 = fmaf(wreg[i+1].w, h1.w, a1);
            a2 = fmaf(wreg[i+2].x, h2.x, a2); a2 = fmaf(wreg[i+2].y, h2.y, a2);
            a2 = fmaf(wreg[i+2].z, h2.z, a2); a2 = fmaf(wreg[i+2].w, h2.w, a2);
            a3 = fmaf(wreg[i+3].x, h3.x, a3); a3 = fmaf(wreg[i+3].y, h3.y, a3);
            a3 = fmaf(wreg[i+3].z, h3.z, a3); a3 = fmaf(wreg[i+3].w, h3.w, a3);
        }
        partial[w][l] = (a0 + a1) + (a2 + a3);
        __syncthreads();

        if (w == 0) {
            float p0 = partial[0][l] + partial[1][l];
            float p1 = partial[2][l] + partial[3][l];
            float p2 = partial[4][l] + partial[5][l];
            float p3 = partial[6][l] + partial[7][l];
            float z  = zpre + ((p0 + p1) + (p2 + p3));
            // MUFU activations: tanh for gate g, sigmoid via 0.5*tanh(z/2)+0.5
            float targ = (g == 2) ? z : 0.5f * z;
            float th;
            asm("tanh.approx.f32 %0, %1;" : "=f"(th) : "f"(targ));
            float a = (g == 2) ? th : fmaf(0.5f, th, 0.5f);
            const unsigned mask = 0xffffffffu;
            float fv = __shfl_sync(mask, a, (l & ~3) + 1);
            float gv = __shfl_sync(mask, a, (l & ~3) + 2);
            float ov = __shfl_sync(mask, a, (l & ~3) + 3);
            if ((l & 3) == 0) {
                c = fmaf(fv, c, a * gv);
                float tc;
                asm("tanh.approx.f32 %0, %1;" : "=f"(tc) : "f"(c));
                float hv = ov * tc;
                hs[t * 1024 + hofs + j0 + u] = hv;   // for downstream GEMMs
                // release-packet: flag (high) + payload (low), ordered after all prior stores
                unsigned long long pkt =
                    (1ULL << 32) | (unsigned long long)__float_as_uint(hv);
                asm volatile("st.release.gpu.global.b64 [%0], %1;"
                             :: "l"(mymb + t * 512 + j0 + u), "l"(pkt) : "memory");
            }
        }
        // next step's first __syncthreads is the post-finalize barrier
    }
}

// ---------------- pairwise scores: out[i][j] = out_b + sum_m tanh(mlp[i][m]+mlp[j+1][m])*w[m] ----------------
__global__ __launch_bounds__(256) void pair_kernel(
    const float* __restrict__ mlp, const float* __restrict__ ow,
    const float* __restrict__ ob, float* __restrict__ out)
{
    __shared__ __align__(16) float Asm[32][132];
    __shared__ float BsmT[128][33];
    __shared__ float wsm[128];

    const int i0 = blockIdx.y * 32;
    const int j0 = blockIdx.x * 32;
    const int tid = threadIdx.x;
    const int ti = tid >> 5;
    const int tj = tid & 31;

    float acc0 = 0.f, acc1 = 0.f, acc2 = 0.f, acc3 = 0.f;

    for (int mc = 0; mc < 512; mc += 128) {
        const int row = tid >> 3, cg = tid & 7;
        {
            const float4* ap = (const float4*)&mlp[(i0 + row) * 512 + mc + cg * 16];
            float4* as = (float4*)&Asm[row][cg * 16];
            #pragma unroll
            for (int q = 0; q < 4; q++) as[q] = ap[q];
        }
        {
            const int brow = j0 + row + 1;
            float4 bp[4];
            if (brow < 512) {
                const float4* bg = (const float4*)&mlp[brow * 512 + mc + cg * 16];
                #pragma unroll
                for (int q = 0; q < 4; q++) bp[q] = bg[q];
            } else {
                float4 zz = make_float4(0.f, 0.f, 0.f, 0.f);
                #pragma unroll
                for (int q = 0; q < 4; q++) bp[q] = zz;
            }
            #pragma unroll
            for (int q = 0; q < 4; q++) {
                BsmT[cg * 16 + q * 4 + 0][row] = bp[q].x;
                BsmT[cg * 16 + q * 4 + 1][row] = bp[q].y;
                BsmT[cg * 16 + q * 4 + 2][row] = bp[q].z;
                BsmT[cg * 16 + q * 4 + 3][row] = bp[q].w;
            }
        }
        if (tid < 128) wsm[tid] = ow[mc + tid];
        __syncthreads();

        #pragma unroll 4
        for (int m = 0; m < 128; m++) {
            float b  = BsmT[m][tj];
            float wv = wsm[m];
            float a0 = Asm[ti][m];
            float a1 = Asm[ti + 8][m];
            float a2 = Asm[ti + 16][m];
            float a3 = Asm[ti + 24][m];
            float t0, t1, t2, t3;
            asm("tanh.approx.f32 %0, %1;" : "=f"(t0) : "f"(a0 + b));
            asm("tanh.approx.f32 %0, %1;" : "=f"(t1) : "f"(a1 + b));
            asm("tanh.approx.f32 %0, %1;" : "=f"(t2) : "f"(a2 + b));
            asm("tanh.approx.f32 %0, %1;" : "=f"(t3) : "f"(a3 + b));
            acc0 = fmaf(t0, wv, acc0);
            acc1 = fmaf(t1, wv, acc1);
            acc2 = fmaf(t2, wv, acc2);
            acc3 = fmaf(t3, wv, acc3);
        }
        __syncthreads();
    }

    const int j = j0 + tj;
    if (j < 511) {
        const float b = __ldg(ob);
        out[(i0 + ti)      * 511 + j] = acc0 + b;
        out[(i0 + ti + 8)  * 511 + j] = acc1 + b;
        out[(i0 + ti + 16) * 511 + j] = acc2 + b;
        out[(i0 + ti + 24) * 511 + j] = acc3 + b;
    }
}

// ---------------- launch ----------------
extern "C" void kernel_launch(void* const* d_in, const int* in_sizes, int n_in,
                              void* d_out, int out_size)
{
    const int*   wi      = (const int*)  d_in[0];
    const int*   pi      = (const int*)  d_in[1];
    const float* wemb    = (const float*)d_in[2];
    const float* pemb    = (const float*)d_in[3];
    const float* Wih0    = (const float*)d_in[4];
    const float* Whh0    = (const float*)d_in[5];
    const float* bih0    = (const float*)d_in[6];
    const float* bhh0    = (const float*)d_in[7];
    const float* Wih0r   = (const float*)d_in[8];
    const float* Whh0r   = (const float*)d_in[9];
    const float* bih0r   = (const float*)d_in[10];
    const float* bhh0r   = (const float*)d_in[11];
    const float* Wih1    = (const float*)d_in[12];
    const float* Whh1    = (const float*)d_in[13];
    const float* bih1    = (const float*)d_in[14];
    const float* bhh1    = (const float*)d_in[15];
    const float* Wih1r   = (const float*)d_in[16];
    const float* Whh1r   = (const float*)d_in[17];
    const float* bih1r   = (const float*)d_in[18];
    const float* bhh1r   = (const float*)d_in[19];
    const float* mlpW    = (const float*)d_in[20];
    const float* mlpBias = (const float*)d_in[21];
    const float* outw    = (const float*)d_in[22];
    const float* outb    = (const float*)d_in[23];

    float *x0, *Za, *Zb, *hs0, *hs1, *mlpbuf;
    unsigned long long *mb0, *mb1;
    cudaGetSymbolAddress((void**)&x0,     g_x0);
    cudaGetSymbolAddress((void**)&Za,     g_Za);
    cudaGetSymbolAddress((void**)&Zb,     g_Zb);
    cudaGetSymbolAddress((void**)&hs0,    g_hs0);
    cudaGetSymbolAddress((void**)&hs1,    g_hs1);
    cudaGetSymbolAddress((void**)&mlpbuf, g_mlp);
    cudaGetSymbolAddress((void**)&mb0,    g_mb0);
    cudaGetSymbolAddress((void**)&mb1,    g_mb1);

    zero_mb_kernel<<<1024, 256>>>();
    embed_kernel<<<LL, 256>>>(wi, pi, wemb, pemb);

    // layer 0 input projections
    gemm_bias_kernel<<<dim3(G4 / 64, LL / 64), 256>>>(x0, Wih0,  bih0,  bhh0,  Za, LL, G4, DIN);
    gemm_bias_kernel<<<dim3(G4 / 64, LL / 64), 256>>>(x0, Wih0r, bih0r, bhh0r, Zb, LL, G4, DIN);
    lstm_rec_kernel<<<128, 256>>>(Za, Zb, Whh0, Whh0r, hs0, mb0);

    // layer 1
    gemm_bias_kernel<<<dim3(G4 / 64, LL / 64), 256>>>(hs0, Wih1,  bih1,  bhh1,  Za, LL, G4, 1024);
    gemm_bias_kernel<<<dim3(G4 / 64, LL / 64), 256>>>(hs0, Wih1r, bih1r, bhh1r, Zb, LL, G4, 1024);
    lstm_rec_kernel<<<128, 256>>>(Za, Zb, Whh1, Whh1r, hs1, mb1);

    // MLP projection
    gemm_bias_kernel<<<dim3(HH / 64, LL / 64), 256>>>(hs1, mlpW, mlpBias, (const float*)nullptr,
                                                      mlpbuf, LL, HH, 1024);
    // pairwise scores
    pair_kernel<<<dim3(16, 16), 256>>>(mlpbuf, outw, outb, (float*)d_out);
}